// round 16
// baseline (speedup 1.0000x reference)
#include <cuda_runtime.h>
#include <math.h>
#include <string.h>

#define BATCH 4
#define CHANS 3
#define HDIM 512
#define WDIM 512
#define NPLANES 32
#define MAX_COC 50.0f
#define KMAX 31
#define HALO 15
#define NSYM 16

#define R 8                          // outputs per thread, stacked in y
#define BTX 32
#define BTY 4
#define NTHREADS (BTX*BTY)           // 128
#define OUTROWS (BTY*R)              // 32
#define TILE_W (BTX + 2*HALO)        // 62
#define TILE_H (OUTROWS + 2*HALO)    // 62
#define NROWS (KMAX + R - 1)         // 38
#define NPQ 8

typedef unsigned long long u64;

__device__ __forceinline__ u64 pk(float lo, float hi) {
    u64 r; asm("mov.b64 %0, {%1, %2};" : "=l"(r) : "f"(lo), "f"(hi)); return r;
}
__device__ __forceinline__ void upk(float& lo, float& hi, u64 v) {
    asm("mov.b64 {%0, %1}, %2;" : "=f"(lo), "=f"(hi) : "l"(v));
}
__device__ __forceinline__ u64 ffma2(u64 a, u64 b, u64 c) {
    u64 d; asm("fma.rn.f32x2 %0, %1, %2, %3;" : "=l"(d) : "l"(a), "l"(b), "l"(c)); return d;
}
__device__ __forceinline__ u64 fmul2(u64 a, u64 b) {
    u64 d; asm("mul.rn.f32x2 %0, %1, %2;" : "=l"(d) : "l"(a), "l"(b)); return d;
}
// Bitcast float2 -> u64 (same aligned register pair; no SASS instruction)
__device__ __forceinline__ u64 as_u64(const float2& v) {
    u64 r; memcpy(&r, &v, 8); return r;
}

__global__ __launch_bounds__(NTHREADS, 2) void dof_kernel(
    const float* __restrict__ img,
    const float* __restrict__ coc,
    float* __restrict__ out)
{
    __shared__ float tile[TILE_H * TILE_W];              // 15376 B
    __shared__ float gs[NSYM * NPLANES];                 // gs[m*32+p]: 2048 B

    const int tx = threadIdx.x, ty = threadIdx.y;
    const int tid = ty * BTX + tx;
    const int bx0 = blockIdx.x * BTX;
    const int by0 = blockIdx.y * OUTROWS;
    const int z   = blockIdx.z;            // z = b*CHANS + ch
    const int b   = z / CHANS;
    const int planeHW = HDIM * WDIM;
    const float step = MAX_COC / (float)(NPLANES - 1);

    // ---- Per-plane symmetric Gaussian half table gs[m][p] ----
    if (tid < NPLANES) {
        const int p = tid;
        float g[KMAX];
        if (p == 0) {
            #pragma unroll
            for (int j = 0; j < KMAX; j++) g[j] = 0.f;
            g[HALO] = 1.f;
        } else {
            const float cocp  = (float)p * step;
            const float sigma = cocp / 2.355f;
            int k = (int)(2.f * cocp + 1.f);
            if ((k & 1) == 0) k++;
            k = min(k, KMAX);
            const int half = k >> 1;
            const float inv2s2 = 1.f / (2.f * sigma * sigma);
            float s = 0.f;
            #pragma unroll
            for (int j = 0; j < KMAX; j++) {
                const int d = j - HALO;
                const int ad = (d < 0) ? -d : d;
                float v = (ad <= half) ? expf(-(float)(d*d) * inv2s2) : 0.f;
                g[j] = v; s += v;
            }
            const float inv = 1.f / s;
            #pragma unroll
            for (int j = 0; j < KMAX; j++) g[j] *= inv;
        }
        #pragma unroll
        for (int m = 0; m < NSYM; m++) gs[m * NPLANES + p] = g[HALO + m];
    }

    // ---- Cooperative tile load (this block's channel, zero-pad) ----
    const float* imgP = img + (size_t)z * planeHW;
    for (int idx = tid; idx < TILE_H * TILE_W; idx += NTHREADS) {
        const int sy = idx / TILE_W;
        const int sx = idx - sy * TILE_W;
        const int gy = by0 - HALO + sy;
        const int gx = bx0 - HALO + sx;
        const bool inb = (gy >= 0) & (gy < HDIM) & (gx >= 0) & (gx < WDIM);
        tile[idx] = inb ? imgP[gy * WDIM + gx] : 0.f;
    }
    __syncthreads();

    const int x   = bx0 + tx;
    const int tyR = ty * R;

    // ---- Per-output plane + packed symmetric weights (gv = register half of hp) ----
    float2 hp[R][NPQ];          // 128 registers of weights
    #pragma unroll
    for (int j = 0; j < R; j++) {
        const int y = by0 + tyR + j;
        float c = coc[b * planeHW + y * WDIM + x];
        int p = (int)floorf(c / step + 0.5f);
        p = max(0, min(NPLANES - 1, p));
        #pragma unroll
        for (int q = 0; q < NPQ; q++) {
            hp[j][q] = make_float2(gs[(2*q) * NPLANES + p],
                                   gs[(2*q + 1) * NPLANES + p]);
        }
    }

    u64 acc[R];
    #pragma unroll
    for (int j = 0; j < R; j++) acc[j] = pk(0.f, 0.f);

    // ---- Main gather: full unroll; EXPLICIT whole-row tap batch (MLP=31) ----
    #pragma unroll
    for (int rr = 0; rr < NROWS; rr++) {
        const float* rowp = tile + (tyR + rr) * TILE_W + tx;

        // Phase 1: batch all 31 taps into registers (back-to-back LDS)
        float tap[KMAX];
        #pragma unroll
        for (int t = 0; t < KMAX; t++) tap[t] = rowp[t];   // tap[t] = t(c - 15 + t)

        // Phase 2: symmetric pre-adds from registers (no memory dependency)
        // tap index of center = HALO; t[c-m] = tap[HALO-m], t[c+m] = tap[HALO+m]
        u64 sp[NPQ];
        sp[0] = pk(tap[HALO], tap[HALO-1] + tap[HALO+1]);
        #pragma unroll
        for (int q = 1; q < NPQ; q++) {
            const int m0 = 2*q, m1 = 2*q + 1;
            sp[q] = pk(tap[HALO-m0] + tap[HALO+m0],
                       tap[HALO-m1] + tap[HALO+m1]);
        }

        // Phase 3: per-output horizontal dot + vertical accumulate
        #pragma unroll
        for (int j = 0; j < R; j++) {
            const int vy = rr - j;                 // compile-time per (rr,j)
            if (vy >= 0 && vy <= KMAX - 1) {
                u64 rsp = fmul2(as_u64(hp[j][0]), sp[0]);
                #pragma unroll
                for (int q = 1; q < NPQ; q++)
                    rsp = ffma2(as_u64(hp[j][q]), sp[q], rsp);
                const int m = (vy >= HALO) ? (vy - HALO) : (HALO - vy);
                const float gv = (m & 1) ? hp[j][m >> 1].y : hp[j][m >> 1].x;
                acc[j] = ffma2(pk(gv, gv), rsp, acc[j]);
            }
        }
    }

    #pragma unroll
    for (int j = 0; j < R; j++) {
        float lo, hi; upk(lo, hi, acc[j]);
        const int y = by0 + tyR + j;
        out[(size_t)z * planeHW + y * WDIM + x] = lo + hi;
    }
}

extern "C" void kernel_launch(void* const* d_in, const int* in_sizes, int n_in,
                              void* d_out, int out_size)
{
    const float* img = (const float*)d_in[0];   // [4,3,512,512]
    const float* coc = (const float*)d_in[1];   // [4,1,512,512]
    float* out = (float*)d_out;                 // [4,3,512,512]

    dim3 block(BTX, BTY);
    dim3 grid(WDIM / BTX, HDIM / OUTROWS, BATCH * CHANS);
    dof_kernel<<<grid, block>>>(img, coc, out);
}